// round 3
// baseline (speedup 1.0000x reference)
#include <cuda_runtime.h>

// Problem constants (fixed by the reference)
static constexpr int       BS    = 64;
static constexpr int       KP1   = 8193;        // K + 1
static constexpr int       FEAT  = 128;
static constexpr long long NDATA = 1000000LL;
static constexpr float     TINV  = 1.0f / 0.07f;

// d_out layout: out_s | out_t | mem_s_new | mem_t_new  (all float32)
static constexpr long long PER       = (long long)BS * KP1;        // 524,352
static constexpr long long OUT_S_OFF = 0;
static constexpr long long OUT_T_OFF = PER;
static constexpr long long MEM_S_OFF = 2 * PER;
static constexpr long long MEM_T_OFF = MEM_S_OFF + NDATA * FEAT;

static constexpr int UNROLL     = 8;            // items per warp in k_contrast
static constexpr int SUM_BLOCKS = 512;

// Scratch (no device allocations allowed)
__device__ double g_part[2][SUM_BLOCKS];        // per-block partial sums
__device__ float  g_inv[2];                     // final scale factors

// JAX without x64 downcasts the reference's int64 indices to int32.
// Detect layout from the first sample_idx words (true i64 values < 2^31
// have zero odd words). 4 cached loads — cheap enough to inline per block.
__device__ __forceinline__ bool detect_i64(const int* __restrict__ w) {
    return (w[1] == 0) && (w[3] == 0) && (w[5] == 0) && (w[7] == 0);
}

__device__ __forceinline__ long long load_index(const void* p, long long i, bool i64) {
    return i64 ? ((const long long*)p)[i]
               : (long long)((const int*)p)[i];
}

// ---------------------------------------------------------------------------
// Contrast: each warp handles UNROLL consecutive items of the flattened
// [0, 2*PER) space. All UNROLL gather loads issued before any reduction
// (MLP = UNROLL). Stores raw exp values; Z computed by k_sum afterwards.
//   item <  PER : out_s = <memory_t[row], feat_s[b]>
//   item >= PER : out_t = <memory_s[row], feat_t[b]>
// ---------------------------------------------------------------------------
__global__ void __launch_bounds__(256)
k_contrast(const float* __restrict__ mem_s, const float* __restrict__ mem_t,
           const float* __restrict__ feat_s, const float* __restrict__ feat_t,
           const void*  __restrict__ sample_idx, float* __restrict__ out)
{
    const bool i64 = detect_i64((const int*)sample_idx);
    const int warp = threadIdx.x >> 5;
    const int lane = threadIdx.x & 31;
    const long long base = ((long long)blockIdx.x * 8 + warp) * UNROLL;

    float4   m[UNROLL];
    int      whicha[UNROLL];
    unsigned locala[UNROLL];
    int      ba[UNROLL];

    // Phase 1: issue all gather loads (independent -> high MLP)
    #pragma unroll
    for (int u = 0; u < UNROLL; u++) {
        const long long item = base + u;
        const int w = (item >= PER) ? 1 : 0;
        const unsigned loc = (unsigned)(item - (long long)w * PER);
        const int b = (int)(loc / (unsigned)KP1);       // mul-shift, 32-bit
        const int k = (int)(loc % (unsigned)KP1);
        const long long row = load_index(sample_idx, (long long)b * KP1 + k, i64);
        const float* __restrict__ mp = w ? mem_s : mem_t;
        m[u] = *(const float4*)(mp + row * FEAT + lane * 4);
        whicha[u] = w; locala[u] = loc; ba[u] = b;
    }

    // Phase 2: dot + warp reduce + exp + store
    #pragma unroll
    for (int u = 0; u < UNROLL; u++) {
        const float* __restrict__ fp = whicha[u] ? feat_t : feat_s;
        const float4 f = *(const float4*)(fp + (long long)ba[u] * FEAT + lane * 4);
        float d = m[u].x * f.x + m[u].y * f.y + m[u].z * f.z + m[u].w * f.w;
        #pragma unroll
        for (int o = 16; o; o >>= 1) d += __shfl_xor_sync(0xffffffffu, d, o);
        if (lane == 0) {
            out[(whicha[u] ? OUT_T_OFF : OUT_S_OFF) + locala[u]] =
                __expf(fminf(d * TINV, 50.0f));
        }
    }
}

// ---------------------------------------------------------------------------
// Sum: grid-stride over both halves, block-reduce, write partials (no atomics
// -> no zero-init kernel needed; deterministic across graph replays).
// ---------------------------------------------------------------------------
__global__ void __launch_bounds__(256)
k_sum(const float* __restrict__ out)
{
    double s0 = 0.0, s1 = 0.0;
    const long long stride = (long long)gridDim.x * blockDim.x;
    for (long long i = (long long)blockIdx.x * blockDim.x + threadIdx.x;
         i < PER; i += stride) {
        s0 += (double)out[i];
        s1 += (double)out[i + PER];
    }
    __shared__ double sh0[256], sh1[256];
    sh0[threadIdx.x] = s0; sh1[threadIdx.x] = s1;
    __syncthreads();
    for (int o = 128; o; o >>= 1) {
        if (threadIdx.x < o) {
            sh0[threadIdx.x] += sh0[threadIdx.x + o];
            sh1[threadIdx.x] += sh1[threadIdx.x + o];
        }
        __syncthreads();
    }
    if (threadIdx.x == 0) {
        g_part[0][blockIdx.x] = sh0[0];
        g_part[1][blockIdx.x] = sh1[0];
    }
}

// ---------------------------------------------------------------------------
// Finalize: single block reduces the partials and computes the two float
// scale factors ONCE (keeps the slow FP64 divide out of the 1M-thread kernel).
// inv = PER / (sum * N_DATA)
// ---------------------------------------------------------------------------
__global__ void __launch_bounds__(SUM_BLOCKS)
k_finalize()
{
    __shared__ double sh0[SUM_BLOCKS], sh1[SUM_BLOCKS];
    const int t = threadIdx.x;
    sh0[t] = g_part[0][t];
    sh1[t] = g_part[1][t];
    __syncthreads();
    for (int o = SUM_BLOCKS / 2; o; o >>= 1) {
        if (t < o) { sh0[t] += sh0[t + o]; sh1[t] += sh1[t + o]; }
        __syncthreads();
    }
    if (t == 0) {
        g_inv[0] = (float)((double)PER / (sh0[0] * (double)NDATA));
        g_inv[1] = (float)((double)PER / (sh1[0] * (double)NDATA));
    }
}

// ---------------------------------------------------------------------------
// Scale: pure float4 stream over the 2*PER outputs. PER % 4 == 0, so the
// which-contrast boundary is float4-aligned.
// ---------------------------------------------------------------------------
__global__ void __launch_bounds__(256)
k_scale(float4* __restrict__ out)
{
    const long long n4 = 2 * PER / 4;                   // 262,176
    const long long i = (long long)blockIdx.x * blockDim.x + threadIdx.x;
    if (i >= n4) return;
    const float inv = g_inv[(i >= PER / 4) ? 1 : 0];
    float4 v = out[i];
    v.x *= inv; v.y *= inv; v.z *= inv; v.w *= inv;
    out[i] = v;
}

// ---------------------------------------------------------------------------
// Bank copy: both 512 MB banks, float4 grid-stride with streaming hints
// (src/dst are never re-read; keep them out of L2).
// ---------------------------------------------------------------------------
__global__ void __launch_bounds__(256)
k_copy(const float4* __restrict__ src_s, const float4* __restrict__ src_t,
       float4* __restrict__ dst_s, float4* __restrict__ dst_t, long long n4)
{
    const long long stride = (long long)gridDim.x * blockDim.x;
    for (long long i = (long long)blockIdx.x * blockDim.x + threadIdx.x;
         i < n4; i += stride) {
        __stcs(dst_s + i, __ldcs(src_s + i));
        __stcs(dst_t + i, __ldcs(src_t + i));
    }
}

// ---------------------------------------------------------------------------
// Momentum update of the 64 touched rows (reads ORIGINAL bank from input,
// writes into the copied output bank — must run after k_copy).
// ---------------------------------------------------------------------------
__global__ void __launch_bounds__(128)
k_update(const float* __restrict__ mem_s, const float* __restrict__ mem_t,
         const float* __restrict__ feat_s, const float* __restrict__ feat_t,
         const void*  __restrict__ idx, float* __restrict__ out)
{
    const bool i64 = detect_i64((const int*)idx);
    const int bank = blockIdx.x >> 6;       // 0 = s-bank, 1 = t-bank
    const int b    = blockIdx.x & 63;
    const int t    = threadIdx.x;           // 0..127

    const float* __restrict__ mem  = bank ? mem_t  : mem_s;
    const float* __restrict__ feat = bank ? feat_t : feat_s;
    float* __restrict__ dst = out + (bank ? MEM_T_OFF : MEM_S_OFF);

    const long long row = load_index(idx, b, i64);
    const float v = mem[row * FEAT + t] * 0.5f + feat[(long long)b * FEAT + t] * 0.5f;

    float s = v * v;
    #pragma unroll
    for (int o = 16; o; o >>= 1) s += __shfl_xor_sync(0xffffffffu, s, o);
    __shared__ float ws[4];
    if ((t & 31) == 0) ws[t >> 5] = s;
    __syncthreads();
    const float tot = ws[0] + ws[1] + ws[2] + ws[3];
    const float inv = 1.0f / fmaxf(sqrtf(tot), 1e-12f);

    dst[row * FEAT + t] = v * inv;
}

// ---------------------------------------------------------------------------
extern "C" void kernel_launch(void* const* d_in, const int* in_sizes, int n_in,
                              void* d_out, int out_size)
{
    const float* feat_s     = (const float*)d_in[0];
    const float* feat_t     = (const float*)d_in[1];
    const void*  idx        = d_in[2];
    const void*  sample_idx = d_in[3];
    const float* mem_s      = (const float*)d_in[4];
    const float* mem_t      = (const float*)d_in[5];
    float* out = (float*)d_out;

    // 2*PER items, 8 warps/block, UNROLL items/warp (exact: 2*PER = 16386*64)
    k_contrast<<<(unsigned)(2 * PER / (8 * UNROLL)), 256>>>(
        mem_s, mem_t, feat_s, feat_t, sample_idx, out);

    k_sum<<<SUM_BLOCKS, 256>>>(out);
    k_finalize<<<1, SUM_BLOCKS>>>();

    k_scale<<<(unsigned)((2 * PER / 4 + 255) / 256), 256>>>((float4*)out);

    const long long n4 = NDATA * FEAT / 4;   // 32M float4 per bank
    k_copy<<<2368, 256>>>((const float4*)mem_s, (const float4*)mem_t,
                          (float4*)(out + MEM_S_OFF), (float4*)(out + MEM_T_OFF), n4);

    k_update<<<128, 128>>>(mem_s, mem_t, feat_s, feat_t, idx, out);
}

// round 4
// speedup vs baseline: 1.1401x; 1.1401x over previous
#include <cuda_runtime.h>

// Problem constants (fixed by the reference)
static constexpr int       BS    = 64;
static constexpr int       KP1   = 8193;        // K + 1
static constexpr int       FEAT  = 128;
static constexpr long long NDATA = 1000000LL;
static constexpr float     TINV  = 1.0f / 0.07f;

// d_out layout: out_s | out_t | mem_s_new | mem_t_new  (all float32)
static constexpr long long PER       = (long long)BS * KP1;        // 524,352
static constexpr long long OUT_S_OFF = 0;
static constexpr long long OUT_T_OFF = PER;
static constexpr long long MEM_S_OFF = 2 * PER;
static constexpr long long MEM_T_OFF = MEM_S_OFF + NDATA * FEAT;

static constexpr int UNROLL     = 8;            // items per warp in k_contrast
static constexpr int SUM_BLOCKS = 512;

// Scratch (no device allocations allowed)
__device__ double g_part[2][SUM_BLOCKS];        // per-block partial sums
__device__ float  g_inv[2];                     // final scale factors

// JAX without x64 downcasts the reference's int64 indices to int32.
// Detect layout from the first sample_idx words (true i64 values < 2^31
// have zero odd words). 4 cached loads — cheap enough to inline per block.
__device__ __forceinline__ bool detect_i64(const int* __restrict__ w) {
    return (w[1] == 0) && (w[3] == 0) && (w[5] == 0) && (w[7] == 0);
}

__device__ __forceinline__ long long load_index(const void* p, long long i, bool i64) {
    return i64 ? ((const long long*)p)[i]
               : (long long)((const int*)p)[i];
}

// ---------------------------------------------------------------------------
// Contrast: each warp handles UNROLL consecutive items of the flattened
// [0, 2*PER) space. All UNROLL gather loads issued before any reduction
// (MLP = UNROLL). Stores raw exp values; Z computed by k_sum afterwards.
//   item <  PER : out_s = <memory_t[row], feat_s[b]>
//   item >= PER : out_t = <memory_s[row], feat_t[b]>
// ---------------------------------------------------------------------------
__global__ void __launch_bounds__(256)
k_contrast(const float* __restrict__ mem_s, const float* __restrict__ mem_t,
           const float* __restrict__ feat_s, const float* __restrict__ feat_t,
           const void*  __restrict__ sample_idx, float* __restrict__ out)
{
    const bool i64 = detect_i64((const int*)sample_idx);
    const int warp = threadIdx.x >> 5;
    const int lane = threadIdx.x & 31;
    const long long base = ((long long)blockIdx.x * 8 + warp) * UNROLL;

    float4   m[UNROLL];
    int      whicha[UNROLL];
    unsigned locala[UNROLL];
    int      ba[UNROLL];

    // Phase 1: issue all gather loads (independent -> high MLP)
    #pragma unroll
    for (int u = 0; u < UNROLL; u++) {
        const long long item = base + u;
        const int w = (item >= PER) ? 1 : 0;
        const unsigned loc = (unsigned)(item - (long long)w * PER);
        const int b = (int)(loc / (unsigned)KP1);       // mul-shift, 32-bit
        const int k = (int)(loc % (unsigned)KP1);
        const long long row = load_index(sample_idx, (long long)b * KP1 + k, i64);
        const float* __restrict__ mp = w ? mem_s : mem_t;
        m[u] = *(const float4*)(mp + row * FEAT + lane * 4);
        whicha[u] = w; locala[u] = loc; ba[u] = b;
    }

    // Phase 2: dot + warp reduce + exp + store
    #pragma unroll
    for (int u = 0; u < UNROLL; u++) {
        const float* __restrict__ fp = whicha[u] ? feat_t : feat_s;
        const float4 f = *(const float4*)(fp + (long long)ba[u] * FEAT + lane * 4);
        float d = m[u].x * f.x + m[u].y * f.y + m[u].z * f.z + m[u].w * f.w;
        #pragma unroll
        for (int o = 16; o; o >>= 1) d += __shfl_xor_sync(0xffffffffu, d, o);
        if (lane == 0) {
            out[(whicha[u] ? OUT_T_OFF : OUT_S_OFF) + locala[u]] =
                __expf(fminf(d * TINV, 50.0f));
        }
    }
}

// ---------------------------------------------------------------------------
// Sum: grid-stride over both halves, block-reduce, write partials (no atomics
// -> no zero-init kernel needed; deterministic across graph replays).
// ---------------------------------------------------------------------------
__global__ void __launch_bounds__(256)
k_sum(const float* __restrict__ out)
{
    double s0 = 0.0, s1 = 0.0;
    const long long stride = (long long)gridDim.x * blockDim.x;
    for (long long i = (long long)blockIdx.x * blockDim.x + threadIdx.x;
         i < PER; i += stride) {
        s0 += (double)out[i];
        s1 += (double)out[i + PER];
    }
    __shared__ double sh0[256], sh1[256];
    sh0[threadIdx.x] = s0; sh1[threadIdx.x] = s1;
    __syncthreads();
    for (int o = 128; o; o >>= 1) {
        if (threadIdx.x < o) {
            sh0[threadIdx.x] += sh0[threadIdx.x + o];
            sh1[threadIdx.x] += sh1[threadIdx.x + o];
        }
        __syncthreads();
    }
    if (threadIdx.x == 0) {
        g_part[0][blockIdx.x] = sh0[0];
        g_part[1][blockIdx.x] = sh1[0];
    }
}

// ---------------------------------------------------------------------------
// Finalize: single block reduces the partials and computes the two float
// scale factors ONCE (keeps the slow FP64 divide out of the wide kernels).
// inv = PER / (sum * N_DATA)
// ---------------------------------------------------------------------------
__global__ void __launch_bounds__(SUM_BLOCKS)
k_finalize()
{
    __shared__ double sh0[SUM_BLOCKS], sh1[SUM_BLOCKS];
    const int t = threadIdx.x;
    sh0[t] = g_part[0][t];
    sh1[t] = g_part[1][t];
    __syncthreads();
    for (int o = SUM_BLOCKS / 2; o; o >>= 1) {
        if (t < o) { sh0[t] += sh0[t + o]; sh1[t] += sh1[t + o]; }
        __syncthreads();
    }
    if (t == 0) {
        g_inv[0] = (float)((double)PER / (sh0[0] * (double)NDATA));
        g_inv[1] = (float)((double)PER / (sh1[0] * (double)NDATA));
    }
}

// ---------------------------------------------------------------------------
// Copy + scale, one launch. Plain cached float4 accesses (streaming hints
// measured SLOWER in R3 — keep default policy).
//  - Prologue: scale the 2*PER contrast outputs by g_inv (4 MB, ~0.2% extra).
//  - Main: grid-stride copy of both 512 MB banks (84% DRAM in R2).
// ---------------------------------------------------------------------------
__global__ void __launch_bounds__(256)
k_copy_scale(const float4* __restrict__ src_s, const float4* __restrict__ src_t,
             float4* __restrict__ dst_s, float4* __restrict__ dst_t,
             float4* __restrict__ outv, long long n4)
{
    const long long stride = (long long)gridDim.x * blockDim.x;
    const long long tid0   = (long long)blockIdx.x * blockDim.x + threadIdx.x;

    // Scale prologue (n4s = 262,176 float4; PER % 4 == 0 so boundary aligns)
    const long long n4s = 2 * PER / 4;
    for (long long i = tid0; i < n4s; i += stride) {
        const float inv = g_inv[(i >= PER / 4) ? 1 : 0];
        float4 v = outv[i];
        v.x *= inv; v.y *= inv; v.z *= inv; v.w *= inv;
        outv[i] = v;
    }

    // Bank copy
    for (long long i = tid0; i < n4; i += stride) {
        dst_s[i] = src_s[i];
        dst_t[i] = src_t[i];
    }
}

// ---------------------------------------------------------------------------
// Momentum update of the 64 touched rows (reads ORIGINAL bank from input,
// writes into the copied output bank — must run after the copy).
// ---------------------------------------------------------------------------
__global__ void __launch_bounds__(128)
k_update(const float* __restrict__ mem_s, const float* __restrict__ mem_t,
         const float* __restrict__ feat_s, const float* __restrict__ feat_t,
         const void*  __restrict__ idx, float* __restrict__ out)
{
    const bool i64 = detect_i64((const int*)idx);
    const int bank = blockIdx.x >> 6;       // 0 = s-bank, 1 = t-bank
    const int b    = blockIdx.x & 63;
    const int t    = threadIdx.x;           // 0..127

    const float* __restrict__ mem  = bank ? mem_t  : mem_s;
    const float* __restrict__ feat = bank ? feat_t : feat_s;
    float* __restrict__ dst = out + (bank ? MEM_T_OFF : MEM_S_OFF);

    const long long row = load_index(idx, b, i64);
    const float v = mem[row * FEAT + t] * 0.5f + feat[(long long)b * FEAT + t] * 0.5f;

    float s = v * v;
    #pragma unroll
    for (int o = 16; o; o >>= 1) s += __shfl_xor_sync(0xffffffffu, s, o);
    __shared__ float ws[4];
    if ((t & 31) == 0) ws[t >> 5] = s;
    __syncthreads();
    const float tot = ws[0] + ws[1] + ws[2] + ws[3];
    const float inv = 1.0f / fmaxf(sqrtf(tot), 1e-12f);

    dst[row * FEAT + t] = v * inv;
}

// ---------------------------------------------------------------------------
extern "C" void kernel_launch(void* const* d_in, const int* in_sizes, int n_in,
                              void* d_out, int out_size)
{
    const float* feat_s     = (const float*)d_in[0];
    const float* feat_t     = (const float*)d_in[1];
    const void*  idx        = d_in[2];
    const void*  sample_idx = d_in[3];
    const float* mem_s      = (const float*)d_in[4];
    const float* mem_t      = (const float*)d_in[5];
    float* out = (float*)d_out;

    // 2*PER items, 8 warps/block, UNROLL items/warp (exact: 2*PER = 16386*64)
    k_contrast<<<(unsigned)(2 * PER / (8 * UNROLL)), 256>>>(
        mem_s, mem_t, feat_s, feat_t, sample_idx, out);

    k_sum<<<SUM_BLOCKS, 256>>>(out);
    k_finalize<<<1, SUM_BLOCKS>>>();

    const long long n4 = NDATA * FEAT / 4;   // 32M float4 per bank
    k_copy_scale<<<2368, 256>>>((const float4*)mem_s, (const float4*)mem_t,
                                (float4*)(out + MEM_S_OFF), (float4*)(out + MEM_T_OFF),
                                (float4*)out, n4);

    k_update<<<128, 128>>>(mem_s, mem_t, feat_s, feat_t, idx, out);
}

// round 6
// speedup vs baseline: 1.2949x; 1.1359x over previous
#include <cuda_runtime.h>

// Problem constants (fixed by the reference)
static constexpr int       BS    = 64;
static constexpr int       KP1   = 8193;        // K + 1
static constexpr int       FEAT  = 128;
static constexpr long long NDATA = 1000000LL;
static constexpr float     TINV  = 1.0f / 0.07f;

// d_out layout: out_s | out_t | mem_s_new | mem_t_new  (all float32)
static constexpr long long PER       = (long long)BS * KP1;        // 524,352
static constexpr long long OUT_S_OFF = 0;
static constexpr long long OUT_T_OFF = PER;
static constexpr long long MEM_S_OFF = 2 * PER;
static constexpr long long MEM_T_OFF = MEM_S_OFF + NDATA * FEAT;

static constexpr int SUM_BLOCKS = 512;
static constexpr int ENT_CAP    = 8;            // bucket capacity per row
static constexpr int OVF_CAP    = 8192;

// Entry packing: k needs 14 bits (KP1 = 8193 > 2^13). b < 64 -> 6 bits.
static constexpr int      K_BITS = 14;
static constexpr unsigned K_MASK = (1u << K_BITS) - 1u;   // 0x3FFF
static_assert(KP1 - 1 <= (int)K_MASK, "k field too narrow");
static_assert(BS - 1 < (1 << (32 - K_BITS)), "b field too narrow");

// Scratch (no device allocations allowed)
__device__ unsigned g_pos[NDATA];               // per-row match count (atomic cursor)
__device__ unsigned g_entries[NDATA * ENT_CAP]; // packed (b<<14)|k per row
__device__ unsigned g_ovf[OVF_CAP];             // overflow: flat sample index i
__device__ unsigned g_ovf_n;
__device__ double   g_part[2][SUM_BLOCKS];      // per-block partial sums
__device__ float    g_inv[2];                   // final scale factors

// JAX without x64 downcasts the reference's int64 indices to int32.
// Detect layout from the first sample_idx words (true i64 values < 2^31
// have zero odd words).
__device__ __forceinline__ bool detect_i64(const int* __restrict__ w) {
    return (w[1] == 0) && (w[3] == 0) && (w[5] == 0) && (w[7] == 0);
}
__device__ __forceinline__ long long load_index(const void* p, long long i, bool i64) {
    return i64 ? ((const long long*)p)[i]
               : (long long)((const int*)p)[i];
}

// Shared dot helper so the main and overflow paths are bitwise identical.
// dt = <row_s, feat_t[b]>, ds = <row_t, feat_s[b]>  (warp-reduced)
__device__ __forceinline__ void dot2_reduce(const float4 vs, const float4 vt,
                                            const float4 ft, const float4 fs,
                                            float& dt, float& ds)
{
    dt = vs.x * ft.x + vs.y * ft.y + vs.z * ft.z + vs.w * ft.w;
    ds = vt.x * fs.x + vt.y * fs.y + vt.z * fs.z + vt.w * fs.w;
    #pragma unroll
    for (int o = 16; o; o >>= 1) {
        dt += __shfl_xor_sync(0xffffffffu, dt, o);
        ds += __shfl_xor_sync(0xffffffffu, ds, o);
    }
}
__device__ __forceinline__ float contrast_val(float d) {
    return __expf(fminf(d * TINV, 50.0f));
}

// ---------------------------------------------------------------------------
// Zero the index cursors (every replay).
// ---------------------------------------------------------------------------
__global__ void __launch_bounds__(256)
k_zero()
{
    const long long i = (long long)blockIdx.x * blockDim.x + threadIdx.x;
    if (i == 0) g_ovf_n = 0;
    for (long long j = i; j < NDATA; j += (long long)gridDim.x * blockDim.x)
        g_pos[j] = 0;
}

// ---------------------------------------------------------------------------
// Build inverted index: for each flat sample i -> row r, append (b,k) to
// row r's bucket; spill to overflow list past ENT_CAP.
// ---------------------------------------------------------------------------
__global__ void __launch_bounds__(256)
k_build(const void* __restrict__ sample_idx)
{
    const bool i64 = detect_i64((const int*)sample_idx);
    const long long i = (long long)blockIdx.x * blockDim.x + threadIdx.x;
    if (i >= PER) return;
    const unsigned b = (unsigned)i / (unsigned)KP1;
    const unsigned k = (unsigned)i % (unsigned)KP1;
    const long long r = load_index(sample_idx, i, i64);
    const unsigned slot = atomicAdd(&g_pos[r], 1u);
    if (slot < ENT_CAP) {
        g_entries[r * ENT_CAP + slot] = (b << K_BITS) | k;
    } else {
        const unsigned o = atomicAdd(&g_ovf_n, 1u);
        if (o < OVF_CAP) g_ovf[o] = (unsigned)i;
    }
}

// ---------------------------------------------------------------------------
// Copy + contrast, fused. One warp per row (grid-stride): stream both banks'
// row (512 B each) through registers to the output banks, and for each
// indexed (b,k) match compute both dots from the in-register rows.
// Stores RAW exp values; Z computed afterwards by k_sum.
// ---------------------------------------------------------------------------
__global__ void __launch_bounds__(256)
k_copy_compute(const float4* __restrict__ mem_s4, const float4* __restrict__ mem_t4,
               float4* __restrict__ dst_s4, float4* __restrict__ dst_t4,
               const float4* __restrict__ feat_s4, const float4* __restrict__ feat_t4,
               float* __restrict__ out)
{
    const int lane = threadIdx.x & 31;
    const long long warpsTotal = (long long)gridDim.x * (blockDim.x >> 5);
    long long w = (long long)blockIdx.x * (blockDim.x >> 5) + (threadIdx.x >> 5);

    for (long long row = w; row < NDATA; row += warpsTotal) {
        const long long base = row * 32 + lane;
        const float4 vs = mem_s4[base];
        const float4 vt = mem_t4[base];
        dst_s4[base] = vs;
        dst_t4[base] = vt;

        unsigned c = g_pos[row];
        if (c) {
            c = c < ENT_CAP ? c : ENT_CAP;
            for (unsigned e = 0; e < c; e++) {
                const unsigned ent = g_entries[row * ENT_CAP + e];
                const unsigned b = ent >> K_BITS;
                const unsigned k = ent & K_MASK;
                const float4 ft = feat_t4[b * 32 + lane];
                const float4 fs = feat_s4[b * 32 + lane];
                float dt, ds;
                dot2_reduce(vs, vt, ft, fs, dt, ds);
                if (lane == 0) {
                    const long long off = (long long)b * KP1 + k;
                    out[OUT_T_OFF + off] = contrast_val(dt);
                    out[OUT_S_OFF + off] = contrast_val(ds);
                }
            }
        }
    }
}

// ---------------------------------------------------------------------------
// Overflow fallback: gather-style, warp per spilled entry. Bitwise-identical
// math to the fused path (shared helpers).
// ---------------------------------------------------------------------------
__global__ void __launch_bounds__(256)
k_ovf(const float4* __restrict__ mem_s4, const float4* __restrict__ mem_t4,
      const float4* __restrict__ feat_s4, const float4* __restrict__ feat_t4,
      const void* __restrict__ sample_idx, float* __restrict__ out)
{
    const bool i64 = detect_i64((const int*)sample_idx);
    const int lane = threadIdx.x & 31;
    const unsigned n = g_ovf_n < OVF_CAP ? g_ovf_n : OVF_CAP;
    const unsigned warpsTotal = gridDim.x * (blockDim.x >> 5);
    for (unsigned e = blockIdx.x * (blockDim.x >> 5) + (threadIdx.x >> 5);
         e < n; e += warpsTotal) {
        const long long i = (long long)g_ovf[e];
        const unsigned b = (unsigned)i / (unsigned)KP1;
        const unsigned k = (unsigned)i % (unsigned)KP1;
        const long long row = load_index(sample_idx, i, i64);
        const float4 vs = mem_s4[row * 32 + lane];
        const float4 vt = mem_t4[row * 32 + lane];
        const float4 ft = feat_t4[b * 32 + lane];
        const float4 fs = feat_s4[b * 32 + lane];
        float dt, ds;
        dot2_reduce(vs, vt, ft, fs, dt, ds);
        if (lane == 0) {
            const long long off = (long long)b * KP1 + k;
            out[OUT_T_OFF + off] = contrast_val(dt);
            out[OUT_S_OFF + off] = contrast_val(ds);
        }
    }
}

// ---------------------------------------------------------------------------
// Sum: grid-stride over both halves of out[], block-reduce, write partials.
// Reads a fixed array in fixed order -> deterministic.
// ---------------------------------------------------------------------------
__global__ void __launch_bounds__(256)
k_sum(const float* __restrict__ out)
{
    double s0 = 0.0, s1 = 0.0;
    const long long stride = (long long)gridDim.x * blockDim.x;
    for (long long i = (long long)blockIdx.x * blockDim.x + threadIdx.x;
         i < PER; i += stride) {
        s0 += (double)out[i];
        s1 += (double)out[i + PER];
    }
    __shared__ double sh0[256], sh1[256];
    sh0[threadIdx.x] = s0; sh1[threadIdx.x] = s1;
    __syncthreads();
    for (int o = 128; o; o >>= 1) {
        if (threadIdx.x < o) {
            sh0[threadIdx.x] += sh0[threadIdx.x + o];
            sh1[threadIdx.x] += sh1[threadIdx.x + o];
        }
        __syncthreads();
    }
    if (threadIdx.x == 0) {
        g_part[0][blockIdx.x] = sh0[0];
        g_part[1][blockIdx.x] = sh1[0];
    }
}

// ---------------------------------------------------------------------------
// Finalize: reduce partials, compute scale factors once.
// inv = PER / (sum * N_DATA)
// ---------------------------------------------------------------------------
__global__ void __launch_bounds__(SUM_BLOCKS)
k_finalize()
{
    __shared__ double sh0[SUM_BLOCKS], sh1[SUM_BLOCKS];
    const int t = threadIdx.x;
    sh0[t] = g_part[0][t];
    sh1[t] = g_part[1][t];
    __syncthreads();
    for (int o = SUM_BLOCKS / 2; o; o >>= 1) {
        if (t < o) { sh0[t] += sh0[t + o]; sh1[t] += sh1[t + o]; }
        __syncthreads();
    }
    if (t == 0) {
        g_inv[0] = (float)((double)PER / (sh0[0] * (double)NDATA));
        g_inv[1] = (float)((double)PER / (sh1[0] * (double)NDATA));
    }
}

// ---------------------------------------------------------------------------
// Scale: pure float4 stream over 2*PER outputs (PER % 4 == 0).
// ---------------------------------------------------------------------------
__global__ void __launch_bounds__(256)
k_scale(float4* __restrict__ outv)
{
    const long long n4 = 2 * PER / 4;
    const long long i = (long long)blockIdx.x * blockDim.x + threadIdx.x;
    if (i >= n4) return;
    const float inv = g_inv[(i >= PER / 4) ? 1 : 0];
    float4 v = outv[i];
    v.x *= inv; v.y *= inv; v.z *= inv; v.w *= inv;
    outv[i] = v;
}

// ---------------------------------------------------------------------------
// Momentum update of the 64 touched rows (reads ORIGINAL bank from input,
// writes into the copied output bank — must run after the copy).
// ---------------------------------------------------------------------------
__global__ void __launch_bounds__(128)
k_update(const float* __restrict__ mem_s, const float* __restrict__ mem_t,
         const float* __restrict__ feat_s, const float* __restrict__ feat_t,
         const void*  __restrict__ idx, float* __restrict__ out)
{
    const bool i64 = detect_i64((const int*)idx);
    const int bank = blockIdx.x >> 6;       // 0 = s-bank, 1 = t-bank
    const int b    = blockIdx.x & 63;
    const int t    = threadIdx.x;           // 0..127

    const float* __restrict__ mem  = bank ? mem_t  : mem_s;
    const float* __restrict__ feat = bank ? feat_t : feat_s;
    float* __restrict__ dst = out + (bank ? MEM_T_OFF : MEM_S_OFF);

    const long long row = load_index(idx, b, i64);
    const float v = mem[row * FEAT + t] * 0.5f + feat[(long long)b * FEAT + t] * 0.5f;

    float s = v * v;
    #pragma unroll
    for (int o = 16; o; o >>= 1) s += __shfl_xor_sync(0xffffffffu, s, o);
    __shared__ float ws[4];
    if ((t & 31) == 0) ws[t >> 5] = s;
    __syncthreads();
    const float tot = ws[0] + ws[1] + ws[2] + ws[3];
    const float inv = 1.0f / fmaxf(sqrtf(tot), 1e-12f);

    dst[row * FEAT + t] = v * inv;
}

// ---------------------------------------------------------------------------
extern "C" void kernel_launch(void* const* d_in, const int* in_sizes, int n_in,
                              void* d_out, int out_size)
{
    const float* feat_s     = (const float*)d_in[0];
    const float* feat_t     = (const float*)d_in[1];
    const void*  idx        = d_in[2];
    const void*  sample_idx = d_in[3];
    const float* mem_s      = (const float*)d_in[4];
    const float* mem_t      = (const float*)d_in[5];
    float* out = (float*)d_out;

    k_zero<<<2048, 256>>>();
    k_build<<<(unsigned)((PER + 255) / 256), 256>>>(sample_idx);

    k_copy_compute<<<2368, 256>>>((const float4*)mem_s, (const float4*)mem_t,
                                  (float4*)(out + MEM_S_OFF), (float4*)(out + MEM_T_OFF),
                                  (const float4*)feat_s, (const float4*)feat_t, out);

    k_ovf<<<8, 256>>>((const float4*)mem_s, (const float4*)mem_t,
                      (const float4*)feat_s, (const float4*)feat_t, sample_idx, out);

    k_sum<<<SUM_BLOCKS, 256>>>(out);
    k_finalize<<<1, SUM_BLOCKS>>>();
    k_scale<<<(unsigned)((2 * PER / 4 + 255) / 256), 256>>>((float4*)out);

    k_update<<<128, 128>>>(mem_s, mem_t, feat_s, feat_t, idx, out);
}

// round 7
// speedup vs baseline: 1.3332x; 1.0296x over previous
#include <cuda_runtime.h>

// Problem constants (fixed by the reference)
static constexpr int       BS    = 64;
static constexpr int       KP1   = 8193;        // K + 1
static constexpr int       FEAT  = 128;
static constexpr long long NDATA = 1000000LL;
static constexpr float     TINV  = 1.0f / 0.07f;

// d_out layout: out_s | out_t | mem_s_new | mem_t_new  (all float32)
static constexpr long long PER       = (long long)BS * KP1;        // 524,352
static constexpr long long OUT_S_OFF = 0;
static constexpr long long OUT_T_OFF = PER;
static constexpr long long MEM_S_OFF = 2 * PER;
static constexpr long long MEM_T_OFF = MEM_S_OFF + NDATA * FEAT;

static constexpr int CC_BLOCKS  = 2368;         // copy_compute grid (16/SM)
static constexpr int ENT_CAP    = 8;            // bucket capacity per row
static constexpr int OVF_CAP    = 8192;
static constexpr int SCALE_BLOCKS = (int)((2 * PER / 4 + 255) / 256);   // 1025

// Entry packing: k needs 14 bits (KP1 = 8193 > 2^13). b < 64 -> 6 bits.
static constexpr int      K_BITS = 14;
static constexpr unsigned K_MASK = (1u << K_BITS) - 1u;
static_assert(KP1 - 1 <= (int)K_MASK, "k field too narrow");
static_assert(BS - 1 < (1 << (32 - K_BITS)), "b field too narrow");

// Scratch (no device allocations allowed)
__device__ unsigned g_pos[NDATA];               // per-row match count (atomic cursor)
__device__ unsigned g_entries[NDATA * ENT_CAP]; // packed (b<<14)|k per row
__device__ unsigned g_ovf[OVF_CAP];             // overflow: flat sample index i
__device__ unsigned g_ovf_n;
__device__ double   g_part[2][CC_BLOCKS];       // per-block partial sums
__device__ float    g_inv[2];                   // final scale factors

// JAX without x64 downcasts the reference's int64 indices to int32.
// Detect from first sample_idx words (true i64 values < 2^31 have zero odd words).
__device__ __forceinline__ bool detect_i64(const int* __restrict__ w) {
    return (w[1] == 0) && (w[3] == 0) && (w[5] == 0) && (w[7] == 0);
}
__device__ __forceinline__ long long load_index(const void* p, long long i, bool i64) {
    return i64 ? ((const long long*)p)[i]
               : (long long)((const int*)p)[i];
}

// Shared dot helper so main and overflow paths are bitwise identical.
// dt = <row_s, feat_t[b]>, ds = <row_t, feat_s[b]>; butterfly leaves the
// reduced value on ALL lanes.
__device__ __forceinline__ void dot2_reduce(const float4 vs, const float4 vt,
                                            const float4 ft, const float4 fs,
                                            float& dt, float& ds)
{
    dt = vs.x * ft.x + vs.y * ft.y + vs.z * ft.z + vs.w * ft.w;
    ds = vt.x * fs.x + vt.y * fs.y + vt.z * fs.z + vt.w * fs.w;
    #pragma unroll
    for (int o = 16; o; o >>= 1) {
        dt += __shfl_xor_sync(0xffffffffu, dt, o);
        ds += __shfl_xor_sync(0xffffffffu, ds, o);
    }
}
__device__ __forceinline__ float contrast_val(float d) {
    return __expf(fminf(d * TINV, 50.0f));
}

// ---------------------------------------------------------------------------
// Zero the index cursors (every replay).
// ---------------------------------------------------------------------------
__global__ void __launch_bounds__(256)
k_zero()
{
    const long long i = (long long)blockIdx.x * blockDim.x + threadIdx.x;
    if (i == 0) g_ovf_n = 0;
    for (long long j = i; j < NDATA; j += (long long)gridDim.x * blockDim.x)
        g_pos[j] = 0;
}

// ---------------------------------------------------------------------------
// Build inverted index: flat sample i -> row r, append (b,k); spill past cap.
// ---------------------------------------------------------------------------
__global__ void __launch_bounds__(256)
k_build(const void* __restrict__ sample_idx)
{
    const bool i64 = detect_i64((const int*)sample_idx);
    const long long i = (long long)blockIdx.x * blockDim.x + threadIdx.x;
    if (i >= PER) return;
    const unsigned b = (unsigned)i / (unsigned)KP1;
    const unsigned k = (unsigned)i % (unsigned)KP1;
    const long long r = load_index(sample_idx, i, i64);
    const unsigned slot = atomicAdd(&g_pos[r], 1u);
    if (slot < ENT_CAP) {
        g_entries[r * ENT_CAP + slot] = (b << K_BITS) | k;
    } else {
        const unsigned o = atomicAdd(&g_ovf_n, 1u);
        if (o < OVF_CAP) g_ovf[o] = (unsigned)i;
    }
}

// ---------------------------------------------------------------------------
// Copy + contrast + Z-partials, fused. One warp per row (grid-stride):
// stream both banks' rows through registers, compute indexed dots from the
// in-register rows, store raw exp values, and accumulate per-warp double
// sums (fixed order -> deterministic). Block tree-reduce -> g_part.
// ---------------------------------------------------------------------------
__global__ void __launch_bounds__(256)
k_copy_compute(const float4* __restrict__ mem_s4, const float4* __restrict__ mem_t4,
               float4* __restrict__ dst_s4, float4* __restrict__ dst_t4,
               const float4* __restrict__ feat_s4, const float4* __restrict__ feat_t4,
               float* __restrict__ out)
{
    const int lane = threadIdx.x & 31;
    const int warp = threadIdx.x >> 5;
    const long long warpsTotal = (long long)gridDim.x * 8;
    const long long w0 = (long long)blockIdx.x * 8 + warp;

    double acc_s = 0.0, acc_t = 0.0;            // identical on all lanes

    for (long long row = w0; row < NDATA; row += warpsTotal) {
        const long long base = row * 32 + lane;
        const float4 vs = mem_s4[base];
        const float4 vt = mem_t4[base];
        dst_s4[base] = vs;
        dst_t4[base] = vt;

        unsigned c = g_pos[row];
        if (c) {
            c = c < ENT_CAP ? c : ENT_CAP;
            for (unsigned e = 0; e < c; e++) {
                const unsigned ent = g_entries[row * ENT_CAP + e];
                const unsigned b = ent >> K_BITS;
                const unsigned k = ent & K_MASK;
                const float4 ft = feat_t4[b * 32 + lane];
                const float4 fs = feat_s4[b * 32 + lane];
                float dt, ds;
                dot2_reduce(vs, vt, ft, fs, dt, ds);
                const float et = contrast_val(dt);
                const float es = contrast_val(ds);
                acc_t += (double)et;
                acc_s += (double)es;
                if (lane == 0) {
                    const long long off = (long long)b * KP1 + k;
                    out[OUT_T_OFF + off] = et;
                    out[OUT_S_OFF + off] = es;
                }
            }
        }
    }

    // Block reduce (one value per warp; lane 0's copy)
    __shared__ double sh_s[8], sh_t[8];
    if (lane == 0) { sh_s[warp] = acc_s; sh_t[warp] = acc_t; }
    __syncthreads();
    if (threadIdx.x == 0) {
        double ts = 0.0, tt = 0.0;
        #pragma unroll
        for (int i = 0; i < 8; i++) { ts += sh_s[i]; tt += sh_t[i]; }
        g_part[0][blockIdx.x] = ts;
        g_part[1][blockIdx.x] = tt;
    }
}

// ---------------------------------------------------------------------------
// Finalize: one block. Reduce the CC_BLOCKS partials; warp 0 then handles the
// (almost always zero) overflow entries with bitwise-identical math, adding
// their contributions; thread 0 computes the scale factors.
// inv = PER / (sum * N_DATA)
// ---------------------------------------------------------------------------
__global__ void __launch_bounds__(512)
k_finalize(const float4* __restrict__ mem_s4, const float4* __restrict__ mem_t4,
           const float4* __restrict__ feat_s4, const float4* __restrict__ feat_t4,
           const void* __restrict__ sample_idx, float* __restrict__ out)
{
    __shared__ double sh0[512], sh1[512];
    __shared__ double ovf_s, ovf_t;
    const int t = threadIdx.x;

    double s0 = 0.0, s1 = 0.0;
    for (int i = t; i < CC_BLOCKS; i += 512) {
        s0 += g_part[0][i];
        s1 += g_part[1][i];
    }
    sh0[t] = s0; sh1[t] = s1;
    __syncthreads();
    for (int o = 256; o; o >>= 1) {
        if (t < o) { sh0[t] += sh0[t + o]; sh1[t] += sh1[t + o]; }
        __syncthreads();
    }

    // Overflow entries: warp 0, sequential (n expected == 0)
    if (t < 32) {
        const int lane = t;
        double os = 0.0, ot = 0.0;
        const unsigned n = g_ovf_n < OVF_CAP ? g_ovf_n : OVF_CAP;
        if (n) {
            const bool i64 = detect_i64((const int*)sample_idx);
            for (unsigned e = 0; e < n; e++) {
                const long long i = (long long)g_ovf[e];
                const unsigned b = (unsigned)i / (unsigned)KP1;
                const unsigned k = (unsigned)i % (unsigned)KP1;
                const long long row = load_index(sample_idx, i, i64);
                const float4 vs = mem_s4[row * 32 + lane];
                const float4 vt = mem_t4[row * 32 + lane];
                const float4 ft = feat_t4[b * 32 + lane];
                const float4 fs = feat_s4[b * 32 + lane];
                float dt, ds;
                dot2_reduce(vs, vt, ft, fs, dt, ds);
                const float et = contrast_val(dt);
                const float es = contrast_val(ds);
                ot += (double)et; os += (double)es;
                if (lane == 0) {
                    const long long off = (long long)b * KP1 + k;
                    out[OUT_T_OFF + off] = et;
                    out[OUT_S_OFF + off] = es;
                }
            }
        }
        if (lane == 0) { ovf_s = os; ovf_t = ot; }
    }
    __syncthreads();
    if (t == 0) {
        const double sum_s = sh0[0] + ovf_s;
        const double sum_t = sh1[0] + ovf_t;
        g_inv[0] = (float)((double)PER / (sum_s * (double)NDATA));
        g_inv[1] = (float)((double)PER / (sum_t * (double)NDATA));
    }
}

// ---------------------------------------------------------------------------
// Epilogue: scale (blocks [0, SCALE_BLOCKS)) + momentum update (last 128
// blocks). Scale: pure float4 stream over 2*PER outputs (PER % 4 == 0).
// Update: reads ORIGINAL bank, overwrites the copied row in d_out.
// ---------------------------------------------------------------------------
__global__ void __launch_bounds__(256)
k_epilogue(const float* __restrict__ mem_s, const float* __restrict__ mem_t,
           const float* __restrict__ feat_s, const float* __restrict__ feat_t,
           const void*  __restrict__ idx, float* __restrict__ out)
{
    if (blockIdx.x < SCALE_BLOCKS) {
        float4* outv = (float4*)out;
        const long long n4 = 2 * PER / 4;
        const long long i = (long long)blockIdx.x * 256 + threadIdx.x;
        if (i < n4) {
            const float inv = g_inv[(i >= PER / 4) ? 1 : 0];
            float4 v = outv[i];
            v.x *= inv; v.y *= inv; v.z *= inv; v.w *= inv;
            outv[i] = v;
        }
        return;
    }

    // Update: 128 work blocks, threads 0..127 active
    const int ub = blockIdx.x - SCALE_BLOCKS;     // [0, 128)
    const int t  = threadIdx.x;
    __shared__ float ws[4];
    if (t < 128) {
        const bool i64 = detect_i64((const int*)idx);
        const int bank = ub >> 6;                 // 0 = s-bank, 1 = t-bank
        const int b    = ub & 63;

        const float* __restrict__ mem  = bank ? mem_t  : mem_s;
        const float* __restrict__ feat = bank ? feat_t : feat_s;
        float* __restrict__ dst = out + (bank ? MEM_T_OFF : MEM_S_OFF);

        const long long row = load_index(idx, b, i64);
        const float v = mem[row * FEAT + t] * 0.5f + feat[(long long)b * FEAT + t] * 0.5f;

        float s = v * v;
        #pragma unroll
        for (int o = 16; o; o >>= 1) s += __shfl_xor_sync(0xffffffffu, s, o);
        if ((t & 31) == 0) ws[t >> 5] = s;
        __syncthreads();
        const float tot = ws[0] + ws[1] + ws[2] + ws[3];
        const float inv = 1.0f / fmaxf(sqrtf(tot), 1e-12f);
        dst[row * FEAT + t] = v * inv;
    } else {
        __syncthreads();
    }
}

// ---------------------------------------------------------------------------
extern "C" void kernel_launch(void* const* d_in, const int* in_sizes, int n_in,
                              void* d_out, int out_size)
{
    const float* feat_s     = (const float*)d_in[0];
    const float* feat_t     = (const float*)d_in[1];
    const void*  idx        = d_in[2];
    const void*  sample_idx = d_in[3];
    const float* mem_s      = (const float*)d_in[4];
    const float* mem_t      = (const float*)d_in[5];
    float* out = (float*)d_out;

    k_zero<<<2048, 256>>>();
    k_build<<<(unsigned)((PER + 255) / 256), 256>>>(sample_idx);

    k_copy_compute<<<CC_BLOCKS, 256>>>((const float4*)mem_s, (const float4*)mem_t,
                                       (float4*)(out + MEM_S_OFF), (float4*)(out + MEM_T_OFF),
                                       (const float4*)feat_s, (const float4*)feat_t, out);

    k_finalize<<<1, 512>>>((const float4*)mem_s, (const float4*)mem_t,
                           (const float4*)feat_s, (const float4*)feat_t,
                           sample_idx, out);

    k_epilogue<<<SCALE_BLOCKS + 128, 256>>>(mem_s, mem_t, feat_s, feat_t, idx, out);
}

// round 8
// speedup vs baseline: 1.3622x; 1.0217x over previous
#include <cuda_runtime.h>

// Problem constants (fixed by the reference)
static constexpr int       BS    = 64;
static constexpr int       KP1   = 8193;        // K + 1
static constexpr int       FEAT  = 128;
static constexpr long long NDATA = 1000000LL;
static constexpr float     TINV  = 1.0f / 0.07f;

// d_out layout: out_s | out_t | mem_s_new | mem_t_new  (all float32)
static constexpr long long PER       = (long long)BS * KP1;        // 524,352
static constexpr long long OUT_S_OFF = 0;
static constexpr long long OUT_T_OFF = PER;
static constexpr long long MEM_S_OFF = 2 * PER;
static constexpr long long MEM_T_OFF = MEM_S_OFF + NDATA * FEAT;

static constexpr int CC_BLOCKS    = 2368;       // copy_compute grid (16/SM)
static constexpr int ENT_CAP      = 8;          // bucket capacity per row
static constexpr int OVF_CAP      = 8192;
static constexpr int SCALE_BLOCKS = (int)((2 * PER / 4 + 255) / 256);   // 1025

// Entry packing: k needs 14 bits (KP1 = 8193 > 2^13). b < 64 -> 6 bits.
static constexpr int      K_BITS = 14;
static constexpr unsigned K_MASK = (1u << K_BITS) - 1u;
static_assert(KP1 - 1 <= (int)K_MASK, "k field too narrow");
static_assert(BS - 1 < (1 << (32 - K_BITS)), "b field too narrow");

// Scratch (no device allocations allowed). g_pos is self-cleaning: zero at
// module load, re-zeroed by k_copy_compute each run after consumption.
__device__ unsigned g_pos[NDATA];               // per-row match count
__device__ unsigned g_entries[NDATA * ENT_CAP]; // packed (b<<14)|k per row
__device__ unsigned g_ovf[OVF_CAP];             // overflow: flat sample index i
__device__ unsigned g_ovf_n;                    // reset by k_inv each run
__device__ double   g_sum[2];                   // Z sums (zeroed by k_build)
__device__ float    g_inv[2];                   // final scale factors

// JAX without x64 downcasts the reference's int64 indices to int32.
// Detect from first sample_idx words (true i64 values < 2^31 have zero odd words).
__device__ __forceinline__ bool detect_i64(const int* __restrict__ w) {
    return (w[1] == 0) && (w[3] == 0) && (w[5] == 0) && (w[7] == 0);
}
__device__ __forceinline__ long long load_index(const void* p, long long i, bool i64) {
    return i64 ? ((const long long*)p)[i]
               : (long long)((const int*)p)[i];
}

// Shared dot helper so main and overflow paths are bitwise identical.
// dt = <row_s, feat_t[b]>, ds = <row_t, feat_s[b]>; butterfly leaves the
// reduced value on ALL lanes.
__device__ __forceinline__ void dot2_reduce(const float4 vs, const float4 vt,
                                            const float4 ft, const float4 fs,
                                            float& dt, float& ds)
{
    dt = vs.x * ft.x + vs.y * ft.y + vs.z * ft.z + vs.w * ft.w;
    ds = vt.x * fs.x + vt.y * fs.y + vt.z * fs.z + vt.w * fs.w;
    #pragma unroll
    for (int o = 16; o; o >>= 1) {
        dt += __shfl_xor_sync(0xffffffffu, dt, o);
        ds += __shfl_xor_sync(0xffffffffu, ds, o);
    }
}
__device__ __forceinline__ float contrast_val(float d) {
    return __expf(fminf(d * TINV, 50.0f));
}

// Process all matches for one row given its in-register data. Accumulates
// raw exp values into acc_s/acc_t (identical across lanes).
__device__ __forceinline__ void process_row(
    long long row, unsigned c,
    const float4 vs, const float4 vt,
    const float4* __restrict__ feat_s4, const float4* __restrict__ feat_t4,
    float* __restrict__ out, int lane, double& acc_s, double& acc_t)
{
    c = c < ENT_CAP ? c : ENT_CAP;
    for (unsigned e = 0; e < c; e++) {
        const unsigned ent = g_entries[row * ENT_CAP + e];
        const unsigned b = ent >> K_BITS;
        const unsigned k = ent & K_MASK;
        const float4 ft = feat_t4[b * 32 + lane];
        const float4 fs = feat_s4[b * 32 + lane];
        float dt, ds;
        dot2_reduce(vs, vt, ft, fs, dt, ds);
        const float et = contrast_val(dt);
        const float es = contrast_val(ds);
        acc_t += (double)et;
        acc_s += (double)es;
        if (lane == 0) {
            const long long off = (long long)b * KP1 + k;
            out[OUT_T_OFF + off] = et;
            out[OUT_S_OFF + off] = es;
        }
    }
}

// ---------------------------------------------------------------------------
// Build inverted index: flat sample i -> row r, append (b,k); spill past cap.
// Also zeroes g_sum for this run (copy_compute's atomics come later).
// ---------------------------------------------------------------------------
__global__ void __launch_bounds__(256)
k_build(const void* __restrict__ sample_idx)
{
    if (blockIdx.x == 0 && threadIdx.x == 0) { g_sum[0] = 0.0; g_sum[1] = 0.0; }
    const bool i64 = detect_i64((const int*)sample_idx);
    const long long i = (long long)blockIdx.x * blockDim.x + threadIdx.x;
    if (i >= PER) return;
    const unsigned b = (unsigned)i / (unsigned)KP1;
    const unsigned k = (unsigned)i % (unsigned)KP1;
    const long long r = load_index(sample_idx, i, i64);
    const unsigned slot = atomicAdd(&g_pos[r], 1u);
    if (slot < ENT_CAP) {
        g_entries[r * ENT_CAP + slot] = (b << K_BITS) | k;
    } else {
        const unsigned o = atomicAdd(&g_ovf_n, 1u);
        if (o < OVF_CAP) g_ovf[o] = (unsigned)i;
    }
}

// ---------------------------------------------------------------------------
// Copy + contrast + Z-sum, fused. One warp per row, 2 rows per iteration:
// both rows' bank loads AND index loads are issued before any stores or
// match work (stream MLP stays high across the index dependency).
// g_pos is zeroed after consumption (self-cleaning for the next run).
// Per-warp double accumulators -> block reduce -> 2 atomicAdd(double)/block.
// ---------------------------------------------------------------------------
__global__ void __launch_bounds__(256)
k_copy_compute(const float4* __restrict__ mem_s4, const float4* __restrict__ mem_t4,
               float4* __restrict__ dst_s4, float4* __restrict__ dst_t4,
               const float4* __restrict__ feat_s4, const float4* __restrict__ feat_t4,
               float* __restrict__ out)
{
    const int lane = threadIdx.x & 31;
    const int warp = threadIdx.x >> 5;
    const long long warpsTotal = (long long)CC_BLOCKS * 8;
    const long long w0 = (long long)blockIdx.x * 8 + warp;

    double acc_s = 0.0, acc_t = 0.0;            // identical on all lanes

    for (long long rowA = w0; rowA < NDATA; rowA += 2 * warpsTotal) {
        const long long rowB = rowA + warpsTotal;
        const bool hasB = (rowB < NDATA);

        // Issue ALL loads first (4 stream float4s + 2 index words)
        const long long baseA = rowA * 32 + lane;
        const float4 vsA = mem_s4[baseA];
        const float4 vtA = mem_t4[baseA];
        float4 vsB, vtB;
        long long baseB = 0;
        if (hasB) {
            baseB = rowB * 32 + lane;
            vsB = mem_s4[baseB];
            vtB = mem_t4[baseB];
        }
        const unsigned cA = g_pos[rowA];
        const unsigned cB = hasB ? g_pos[rowB] : 0u;

        // Stores
        dst_s4[baseA] = vsA;
        dst_t4[baseA] = vtA;
        if (hasB) {
            dst_s4[baseB] = vsB;
            dst_t4[baseB] = vtB;
        }

        // Reset index for next run (single lane)
        if (lane == 0) {
            if (cA) g_pos[rowA] = 0u;
            if (cB) g_pos[rowB] = 0u;
        }

        // Match work
        if (cA) process_row(rowA, cA, vsA, vtA, feat_s4, feat_t4, out, lane, acc_s, acc_t);
        if (cB) process_row(rowB, cB, vsB, vtB, feat_s4, feat_t4, out, lane, acc_s, acc_t);
    }

    // Block reduce (one value per warp; lane 0's copy), then 2 atomics/block
    __shared__ double sh_s[8], sh_t[8];
    if (lane == 0) { sh_s[warp] = acc_s; sh_t[warp] = acc_t; }
    __syncthreads();
    if (threadIdx.x == 0) {
        double ts = 0.0, tt = 0.0;
        #pragma unroll
        for (int i = 0; i < 8; i++) { ts += sh_s[i]; tt += sh_t[i]; }
        atomicAdd(&g_sum[0], ts);
        atomicAdd(&g_sum[1], tt);
    }
}

// ---------------------------------------------------------------------------
// Inv: one warp. Handle the (almost always zero) overflow entries with
// bitwise-identical math, compute scale factors, reset overflow cursor.
// inv = PER / (sum * N_DATA)
// ---------------------------------------------------------------------------
__global__ void __launch_bounds__(32)
k_inv(const float4* __restrict__ mem_s4, const float4* __restrict__ mem_t4,
      const float4* __restrict__ feat_s4, const float4* __restrict__ feat_t4,
      const void* __restrict__ sample_idx, float* __restrict__ out)
{
    const int lane = threadIdx.x;
    double os = 0.0, ot = 0.0;                  // identical on all lanes
    const unsigned n = g_ovf_n < OVF_CAP ? g_ovf_n : OVF_CAP;
    if (n) {
        const bool i64 = detect_i64((const int*)sample_idx);
        for (unsigned e = 0; e < n; e++) {
            const long long i = (long long)g_ovf[e];
            const unsigned b = (unsigned)i / (unsigned)KP1;
            const unsigned k = (unsigned)i % (unsigned)KP1;
            const long long row = load_index(sample_idx, i, i64);
            const float4 vs = mem_s4[row * 32 + lane];
            const float4 vt = mem_t4[row * 32 + lane];
            const float4 ft = feat_t4[b * 32 + lane];
            const float4 fs = feat_s4[b * 32 + lane];
            float dt, ds;
            dot2_reduce(vs, vt, ft, fs, dt, ds);
            const float et = contrast_val(dt);
            const float es = contrast_val(ds);
            ot += (double)et; os += (double)es;
            if (lane == 0) {
                const long long off = (long long)b * KP1 + k;
                out[OUT_T_OFF + off] = et;
                out[OUT_S_OFF + off] = es;
            }
        }
    }
    if (lane == 0) {
        const double sum_s = g_sum[0] + os;
        const double sum_t = g_sum[1] + ot;
        g_inv[0] = (float)((double)PER / (sum_s * (double)NDATA));
        g_inv[1] = (float)((double)PER / (sum_t * (double)NDATA));
        g_ovf_n = 0u;                           // reset for next run
    }
}

// ---------------------------------------------------------------------------
// Epilogue: scale (blocks [0, SCALE_BLOCKS)) + momentum update (last 128
// blocks). Scale: pure float4 stream over 2*PER outputs (PER % 4 == 0).
// Update: reads ORIGINAL bank, overwrites the copied row in d_out.
// ---------------------------------------------------------------------------
__global__ void __launch_bounds__(256)
k_epilogue(const float* __restrict__ mem_s, const float* __restrict__ mem_t,
           const float* __restrict__ feat_s, const float* __restrict__ feat_t,
           const void*  __restrict__ idx, float* __restrict__ out)
{
    if (blockIdx.x < SCALE_BLOCKS) {
        float4* outv = (float4*)out;
        const long long n4 = 2 * PER / 4;
        const long long i = (long long)blockIdx.x * 256 + threadIdx.x;
        if (i < n4) {
            const float inv = g_inv[(i >= PER / 4) ? 1 : 0];
            float4 v = outv[i];
            v.x *= inv; v.y *= inv; v.z *= inv; v.w *= inv;
            outv[i] = v;
        }
        return;
    }

    // Update: 128 work blocks, threads 0..127 active
    const int ub = blockIdx.x - SCALE_BLOCKS;     // [0, 128)
    const int t  = threadIdx.x;
    __shared__ float ws[4];
    if (t < 128) {
        const bool i64 = detect_i64((const int*)idx);
        const int bank = ub >> 6;                 // 0 = s-bank, 1 = t-bank
        const int b    = ub & 63;

        const float* __restrict__ mem  = bank ? mem_t  : mem_s;
        const float* __restrict__ feat = bank ? feat_t : feat_s;
        float* __restrict__ dst = out + (bank ? MEM_T_OFF : MEM_S_OFF);

        const long long row = load_index(idx, b, i64);
        const float v = mem[row * FEAT + t] * 0.5f + feat[(long long)b * FEAT + t] * 0.5f;

        float s = v * v;
        #pragma unroll
        for (int o = 16; o; o >>= 1) s += __shfl_xor_sync(0xffffffffu, s, o);
        if ((t & 31) == 0) ws[t >> 5] = s;
        __syncthreads();
        const float tot = ws[0] + ws[1] + ws[2] + ws[3];
        const float inv = 1.0f / fmaxf(sqrtf(tot), 1e-12f);
        dst[row * FEAT + t] = v * inv;
    } else {
        __syncthreads();
    }
}

// ---------------------------------------------------------------------------
extern "C" void kernel_launch(void* const* d_in, const int* in_sizes, int n_in,
                              void* d_out, int out_size)
{
    const float* feat_s     = (const float*)d_in[0];
    const float* feat_t     = (const float*)d_in[1];
    const void*  idx        = d_in[2];
    const void*  sample_idx = d_in[3];
    const float* mem_s      = (const float*)d_in[4];
    const float* mem_t      = (const float*)d_in[5];
    float* out = (float*)d_out;

    k_build<<<(unsigned)((PER + 255) / 256), 256>>>(sample_idx);

    k_copy_compute<<<CC_BLOCKS, 256>>>((const float4*)mem_s, (const float4*)mem_t,
                                       (float4*)(out + MEM_S_OFF), (float4*)(out + MEM_T_OFF),
                                       (const float4*)feat_s, (const float4*)feat_t, out);

    k_inv<<<1, 32>>>((const float4*)mem_s, (const float4*)mem_t,
                     (const float4*)feat_s, (const float4*)feat_t,
                     sample_idx, out);

    k_epilogue<<<SCALE_BLOCKS + 128, 256>>>(mem_s, mem_t, feat_s, feat_t, idx, out);
}